// round 6
// baseline (speedup 1.0000x reference)
#include <cuda_runtime.h>

// Windowed local attention, k=7, H=W=256, C=32, fp32.
// 128 thr / 32x4 tile, 1 thread per pixel. Both halos (ref+val) staged via
// cp.async.cg into separate buffers at kernel start; pass1 overlaps val
// staging. Layout [g=c/4][pos][c%4] -> LDS.128 = 4 channels per load.

#define H_IMG 256
#define W_IMG 256
#define C 32
#define K 7
#define PAD 3
#define TX 32
#define TY 4
#define HW 38              // TX + K - 1
#define HH 10              // TY + K - 1
#define NPOS (HW * HH)     // 380
#define NG 8               // channel groups of 4
#define GSTRIDE (NPOS * 4) // floats per group
#define TBYTES (NG * GSTRIDE * 4)   // 48640 per tensor
#define NTHREADS 128
#define SMEM_BYTES (2 * TBYTES)     // 97280

__device__ __forceinline__ void cp16(float* dst_smem, const float* src, bool valid) {
    unsigned int d = (unsigned int)__cvta_generic_to_shared(dst_smem);
    int sz = valid ? 16 : 0;
    asm volatile("cp.async.cg.shared.global [%0], [%1], 16, %2;"
                 :: "r"(d), "l"(src), "r"(sz));
}
__device__ __forceinline__ void cp_commit() {
    asm volatile("cp.async.commit_group;");
}
template <int N>
__device__ __forceinline__ void cp_wait() {
    asm volatile("cp.async.wait_group %0;" :: "n"(N));
}

// Issue cp.asyncs for one tensor's halo: [g][pos][j] layout, zero-fill OOB.
__device__ __forceinline__ void stage_async(float* __restrict__ buf,
                                            const float* __restrict__ src,
                                            int bx, int by, int tid) {
    for (int idx = tid; idx < NPOS * NG; idx += NTHREADS) {
        int g  = idx / NPOS;
        int s  = idx - g * NPOS;
        int wp = s % HW;
        int hp = s / HW;
        int gw = bx * TX - PAD + wp;
        int gh = by * TY - PAD + hp;
        bool ok = (gw >= 0) && (gw < W_IMG) && (gh >= 0) && (gh < H_IMG);
        const float* sp = ok ? (src + ((gh << 8) + gw) * C + (g << 2)) : src;
        cp16(buf + g * GSTRIDE + s * 4, sp, ok);
    }
}

__global__ __launch_bounds__(NTHREADS, 2)
void local_attn_kernel(const float* __restrict__ main_in,
                       const float* __restrict__ ref_in,
                       const float* __restrict__ val_in,
                       float* __restrict__ out) {
    extern __shared__ float smem[];
    float* bufR = smem;                       // ref halo
    float* bufV = smem + NG * GSTRIDE;        // val halo

    const int tid = threadIdx.x;
    const int bx = blockIdx.x, by = blockIdx.y;
    const int px = tid & 31;
    const int py = tid >> 5;
    const int s0 = py * HW + px;
    const int gpix = (((by * TY + py) << 8) + bx * TX + px) * C;

    // ---- Kick off BOTH halo copies up front ----
    stage_async(bufR, ref_in, bx, by, tid);
    cp_commit();                              // group: ref
    stage_async(bufV, val_in, bx, by, tid);
    cp_commit();                              // group: val

    // ---- Query loads overlap the copies ----
    float q[C];
    #pragma unroll
    for (int i = 0; i < C / 4; i++) {
        float4 t = *reinterpret_cast<const float4*>(main_in + gpix + 4 * i);
        q[4 * i + 0] = t.x;
        q[4 * i + 1] = t.y;
        q[4 * i + 2] = t.z;
        q[4 * i + 3] = t.w;
    }

    // ---- Wait for ref only (val still streaming) ----
    cp_wait<1>();
    __syncthreads();

    // ---- Pass 1: scores, g-outer, 49 independent accumulators ----
    float sc[K * K];
    #pragma unroll
    for (int p = 0; p < K * K; p++) sc[p] = 0.f;

    #pragma unroll
    for (int g = 0; g < NG; g++) {
        const float* rb = bufR + g * GSTRIDE;
        float q0 = q[4 * g + 0], q1 = q[4 * g + 1];
        float q2 = q[4 * g + 2], q3 = q[4 * g + 3];
        #pragma unroll
        for (int dh = 0; dh < K; dh++) {
            #pragma unroll
            for (int dw = 0; dw < K; dw++) {
                float4 r = *reinterpret_cast<const float4*>(
                    rb + (s0 + dh * HW + dw) * 4);
                float a = fmaf(r.x, q0, r.y * q1);
                float b = fmaf(r.z, q2, r.w * q3);
                sc[dh * K + dw] += a + b;
            }
        }
    }

    // ---- Softmax over 49 (OOB positions carry score 0, included) ----
    float mx = sc[0];
    #pragma unroll
    for (int p = 1; p < K * K; p++) mx = fmaxf(mx, sc[p]);
    float sum = 0.f;
    #pragma unroll
    for (int p = 0; p < K * K; p++) {
        sc[p] = __expf(sc[p] - mx);
        sum += sc[p];
    }
    float inv = 1.f / sum;
    #pragma unroll
    for (int p = 0; p < K * K; p++) sc[p] *= inv;

    // ---- Val copies should already be done; make them visible ----
    cp_wait<0>();
    __syncthreads();

    // ---- Pass 2: g-outer, 4-channel accumulators, direct store ----
    #pragma unroll
    for (int g = 0; g < NG; g++) {
        const float* vb = bufV + g * GSTRIDE;
        float a0 = 0.f, a1 = 0.f, a2 = 0.f, a3 = 0.f;
        #pragma unroll
        for (int dh = 0; dh < K; dh++) {
            #pragma unroll
            for (int dw = 0; dw < K; dw++) {
                float w = sc[dh * K + dw];
                float4 v = *reinterpret_cast<const float4*>(
                    vb + (s0 + dh * HW + dw) * 4);
                a0 = fmaf(v.x, w, a0);
                a1 = fmaf(v.y, w, a1);
                a2 = fmaf(v.z, w, a2);
                a3 = fmaf(v.w, w, a3);
            }
        }
        *reinterpret_cast<float4*>(out + gpix + (g << 2)) =
            make_float4(a0, a1, a2, a3);
    }
}

extern "C" void kernel_launch(void* const* d_in, const int* in_sizes, int n_in,
                              void* d_out, int out_size) {
    const float* main_in = (const float*)d_in[0];
    const float* ref_in  = (const float*)d_in[1];
    const float* val_in  = (const float*)d_in[2];
    float* out = (float*)d_out;

    cudaFuncSetAttribute(local_attn_kernel,
                         cudaFuncAttributeMaxDynamicSharedMemorySize, SMEM_BYTES);

    dim3 grid(W_IMG / TX, H_IMG / TY);
    local_attn_kernel<<<grid, NTHREADS, SMEM_BYTES>>>(main_in, ref_in, val_in, out);
}

// round 7
// speedup vs baseline: 1.2811x; 1.2811x over previous
#include <cuda_runtime.h>

// Windowed local attention, k=7, H=W=256, C=32, fp32.
// 2 vertically-adjacent pixels per thread: 8x7 union window (56 loads serve
// 98 MACs) -> 43% less smem crossbar traffic. Tile 32x8, 128 thr, halo 38x14,
// single 68KB buffer reused ref -> val.

#define H_IMG 256
#define W_IMG 256
#define C 32
#define K 7
#define PAD 3
#define TX 32
#define TY 8               // 2 rows per warp
#define HW 38              // TX + K - 1
#define HH 14              // TY + K - 1
#define NPOS (HW * HH)     // 532
#define CS 533             // row stride (odd -> conflict-free staging)
#define NTHREADS 128
#define SMEM_BYTES (C * CS * 4)   // 68224

// Stage one tensor's halo: [c][pos] channel-major, zero-padded OOB.
__device__ __forceinline__ void stage_halo(float* __restrict__ buf,
                                           const float* __restrict__ src,
                                           int bx, int by, int tid) {
    for (int idx = tid; idx < NPOS * (C / 4); idx += NTHREADS) {
        int g  = idx & 7;                 // 4-channel group
        int s  = idx >> 3;                // halo position
        int wp = s % HW;
        int hp = s / HW;
        int gw = bx * TX - PAD + wp;
        int gh = by * TY - PAD + hp;
        float4 r = make_float4(0.f, 0.f, 0.f, 0.f);
        if (gw >= 0 && gw < W_IMG && gh >= 0 && gh < H_IMG) {
            r = *reinterpret_cast<const float4*>(src + ((gh << 8) + gw) * C + (g << 2));
        }
        int c0 = g << 2;
        buf[(c0 + 0) * CS + s] = r.x;
        buf[(c0 + 1) * CS + s] = r.y;
        buf[(c0 + 2) * CS + s] = r.z;
        buf[(c0 + 3) * CS + s] = r.w;
    }
}

__global__ __launch_bounds__(NTHREADS, 3)
void local_attn_kernel(const float* __restrict__ main_in,
                       const float* __restrict__ ref_in,
                       const float* __restrict__ val_in,
                       float* __restrict__ out) {
    extern __shared__ float smem[];
    float* buf = smem;

    const int tid  = threadIdx.x;
    const int bx   = blockIdx.x, by = blockIdx.y;
    const int lane = tid & 31;           // px
    const int warp = tid >> 5;           // owns tile rows 2w, 2w+1
    const int h0   = warp << 1;          // first tile row
    const int s0   = h0 * HW + lane;     // window origin for pixel 0

    const int gy0  = by * TY + h0;
    const int gpix0 = ((gy0 << 8) + bx * TX + lane) * C;
    const int gpix1 = gpix0 + (W_IMG * C);   // row below

    // ---- Stage ref halo ----
    stage_halo(buf, ref_in, bx, by, tid);
    __syncthreads();

    // ---- Pass 1: scores for both pixels, 2 chunks of 16 channels ----
    float sc0[K * K], sc1[K * K];
    #pragma unroll
    for (int p = 0; p < K * K; p++) { sc0[p] = 0.f; sc1[p] = 0.f; }

    #pragma unroll
    for (int cc = 0; cc < 2; cc++) {
        float q0[16], q1[16];
        #pragma unroll
        for (int i = 0; i < 4; i++) {
            float4 a = *reinterpret_cast<const float4*>(main_in + gpix0 + cc * 16 + 4 * i);
            float4 b = *reinterpret_cast<const float4*>(main_in + gpix1 + cc * 16 + 4 * i);
            q0[4 * i + 0] = a.x; q0[4 * i + 1] = a.y; q0[4 * i + 2] = a.z; q0[4 * i + 3] = a.w;
            q1[4 * i + 0] = b.x; q1[4 * i + 1] = b.y; q1[4 * i + 2] = b.z; q1[4 * i + 3] = b.w;
        }
        #pragma unroll
        for (int c = 0; c < 16; c++) {
            const float* base = buf + (cc * 16 + c) * CS + s0;
            #pragma unroll
            for (int dh = 0; dh < K + 1; dh++) {     // union: 8 rows
                #pragma unroll
                for (int dw = 0; dw < K; dw++) {
                    float v = base[dh * HW + dw];
                    if (dh < K)  sc0[dh * K + dw]       = fmaf(v, q0[c], sc0[dh * K + dw]);
                    if (dh >= 1) sc1[(dh - 1) * K + dw] = fmaf(v, q1[c], sc1[(dh - 1) * K + dw]);
                }
            }
        }
    }

    // ---- Softmax (OOB positions carry score 0, included) ----
    {
        float mx0 = sc0[0], mx1 = sc1[0];
        #pragma unroll
        for (int p = 1; p < K * K; p++) { mx0 = fmaxf(mx0, sc0[p]); mx1 = fmaxf(mx1, sc1[p]); }
        float s0m = 0.f, s1m = 0.f;
        #pragma unroll
        for (int p = 0; p < K * K; p++) {
            sc0[p] = __expf(sc0[p] - mx0); s0m += sc0[p];
            sc1[p] = __expf(sc1[p] - mx1); s1m += sc1[p];
        }
        float i0 = 1.f / s0m, i1 = 1.f / s1m;
        #pragma unroll
        for (int p = 0; p < K * K; p++) { sc0[p] *= i0; sc1[p] *= i1; }
    }

    // ---- Stage val halo (reuse buffer) ----
    __syncthreads();
    stage_halo(buf, val_in, bx, by, tid);
    __syncthreads();

    // ---- Pass 2: outputs for both pixels, 4-channel groups ----
    #pragma unroll
    for (int g = 0; g < 8; g++) {
        float a0[4] = {0.f, 0.f, 0.f, 0.f};
        float a1[4] = {0.f, 0.f, 0.f, 0.f};
        #pragma unroll
        for (int c = 0; c < 4; c++) {
            const float* base = buf + ((g << 2) + c) * CS + s0;
            #pragma unroll
            for (int dh = 0; dh < K + 1; dh++) {
                #pragma unroll
                for (int dw = 0; dw < K; dw++) {
                    float v = base[dh * HW + dw];
                    if (dh < K)  a0[c] = fmaf(v, sc0[dh * K + dw], a0[c]);
                    if (dh >= 1) a1[c] = fmaf(v, sc1[(dh - 1) * K + dw], a1[c]);
                }
            }
        }
        *reinterpret_cast<float4*>(out + gpix0 + (g << 2)) = make_float4(a0[0], a0[1], a0[2], a0[3]);
        *reinterpret_cast<float4*>(out + gpix1 + (g << 2)) = make_float4(a1[0], a1[1], a1[2], a1[3]);
    }
}

extern "C" void kernel_launch(void* const* d_in, const int* in_sizes, int n_in,
                              void* d_out, int out_size) {
    const float* main_in = (const float*)d_in[0];
    const float* ref_in  = (const float*)d_in[1];
    const float* val_in  = (const float*)d_in[2];
    float* out = (float*)d_out;

    cudaFuncSetAttribute(local_attn_kernel,
                         cudaFuncAttributeMaxDynamicSharedMemorySize, SMEM_BYTES);

    dim3 grid(W_IMG / TX, H_IMG / TY);
    local_attn_kernel<<<grid, NTHREADS, SMEM_BYTES>>>(main_in, ref_in, val_in, out);
}